// round 15
// baseline (speedup 1.0000x reference)
#include <cuda_runtime.h>
#include <cuda_bf16.h>
#include <cstdint>

#define NN 8192
#define DIN 256
#define DOUT 32
#define NPART 128            // pool partial blocks (64 rows each)
#define NCHUNK 128           // per K-half: 4096/32

__device__ __align__(16) __nv_bfloat16 g_Bhi[DOUT * NN];
__device__ __align__(16) __nv_bfloat16 g_Blo[DOUT * NN];
__device__ float    g_logits[NN * DOUT];
__device__ unsigned g_colmax_bits[DOUT];
__device__ float    g_sumpart[NPART * DOUT];
__device__ float    g_part[NPART * DOUT * DIN];

// ---------------- helpers ----------------
__device__ __forceinline__ unsigned long long pack2(float x) {
    unsigned long long r; asm("mov.b64 %0, {%1, %1};" : "=l"(r) : "f"(x)); return r;
}
__device__ __forceinline__ unsigned long long ffma2(unsigned long long a,
                                                    unsigned long long b,
                                                    unsigned long long c) {
    unsigned long long d;
    asm("fma.rn.f32x2 %0, %1, %2, %3;" : "=l"(d) : "l"(a), "l"(b), "l"(c));
    return d;
}
__device__ __forceinline__ float2 unpack2(unsigned long long v) {
    float2 f; asm("mov.b64 {%0, %1}, %2;" : "=f"(f.x), "=f"(f.y) : "l"(v)); return f;
}
__device__ __forceinline__ unsigned fkey(float f) {
    int b = __float_as_int(f);
    return (unsigned)(b ^ ((b >> 31) | 0x80000000));
}
__device__ __forceinline__ float funkey(unsigned u) {
    int b = (u & 0x80000000u) ? (int)(u ^ 0x80000000u) : ~(int)u;
    return __int_as_float(b);
}
__device__ __forceinline__ void split2t(float2 v, uint32_t& hi, uint32_t& lo) {
    uint32_t u0 = __float_as_uint(v.x), u1 = __float_as_uint(v.y);
    asm("prmt.b32 %0, %1, %2, 0x7632;" : "=r"(hi) : "r"(u0), "r"(u1));
    float l0 = v.x - __uint_as_float(u0 & 0xFFFF0000u);
    float l1 = v.y - __uint_as_float(u1 & 0xFFFF0000u);
    asm("cvt.rn.bf16x2.f32 %0, %1, %2;" : "=r"(lo) : "f"(l1), "f"(l0));
}
__device__ __forceinline__ uint32_t smem_u32(const void* p) {
    uint32_t a;
    asm("{ .reg .u64 t; cvta.to.shared.u64 t, %1; cvt.u32.u64 %0, t; }"
        : "=r"(a) : "l"(p));
    return a;
}
__device__ __forceinline__ void mma_bf16(float& c0, float& c1, float& c2, float& c3,
                                         uint32_t a0, uint32_t a1, uint32_t a2,
                                         uint32_t a3, uint32_t b0, uint32_t b1) {
    asm volatile(
        "mma.sync.aligned.m16n8k16.row.col.f32.bf16.bf16.f32 "
        "{%0,%1,%2,%3}, {%4,%5,%6,%7}, {%8,%9}, {%0,%1,%2,%3};"
        : "+f"(c0), "+f"(c1), "+f"(c2), "+f"(c3)
        : "r"(a0), "r"(a1), "r"(a2), "r"(a3), "r"(b0), "r"(b1));
}
#define CP16(sm, gp) asm volatile( \
    "cp.async.cg.shared.global [%0], [%1], 16;" :: "r"(sm), "l"(gp) : "memory")
#define CP_COMMIT() asm volatile("cp.async.commit_group;" ::: "memory")
#define CP_WAIT1()  asm volatile("cp.async.wait_group 1;" ::: "memory")

// ---------------------------------------------------------------------------
// gemm2 (warp-autonomous): 128 CTAs x 64 rows, 8 warps = 4 m16-tiles x 2
// K-halves. Each warp has a PRIVATE 3-slot ring (A 16x32k fp32 + its own copy
// of B hi/lo) and synchronizes only via its own cp.async groups + __syncwarp.
// NO __syncthreads in the mainloop.
// Slot layout (uint32 words): A [16r][36] @0 ; Bhi [32n][20] @576 ; Blo @1216.
// ---------------------------------------------------------------------------
#define WSLOT 1856
#define WRING 3
#define GEMM2_SMEM (8 * WRING * WSLOT * 4)    // 178176 B

__global__ void __launch_bounds__(256, 1)
gemm2_kernel(const float* __restrict__ A)
{
    extern __shared__ uint32_t smu[];
    __shared__ unsigned smax[DOUT];
    const int t = threadIdx.x;
    const int w = t >> 5, lane = t & 31;
    const int gid = lane >> 2, t4 = lane & 3;
    const int mt = w & 3, half = w >> 2;
    const int rb = blockIdx.x * 64;
    const int k0 = half * 4096;
    const uint32_t* __restrict__ BHg = (const uint32_t*)g_Bhi;
    const uint32_t* __restrict__ BLg = (const uint32_t*)g_Blo;
    const uint32_t wbase = smem_u32(smu) + 4u * (uint32_t)(w * WRING * WSLOT);
    uint32_t* const wbuf = smu + w * WRING * WSLOT;

    if (t < DOUT) smax[t] = 0u;

    // per-lane cp.async descriptors
    // A: 128 cp16/chunk -> 4/lane. f = lane + j*32: row = f>>3, seg = f&7
    const float* gA[4]; uint32_t sAo[4];
#pragma unroll
    for (int j = 0; j < 4; j++) {
        int f = lane + j * 32, row = f >> 3, seg = f & 7;
        gA[j] = A + (size_t)(rb + mt * 16 + row) * NN + k0 + seg * 4;
        sAo[j] = 4u * (uint32_t)(row * 36 + seg * 4);
    }
    // B: 256 cp16/chunk -> 8/lane. f = lane + j*32: arr=f>>7, n=(f&127)>>2, sg=f&3
    const uint32_t* gB[8]; uint32_t sBo[8];
#pragma unroll
    for (int j = 0; j < 8; j++) {
        int f = lane + j * 32, arr = f >> 7, rem = f & 127;
        int n = rem >> 2, sg = rem & 3;
        gB[j] = (arr ? BLg : BHg) + n * (NN / 2) + half * 2048 + sg * 4;
        sBo[j] = 4u * (uint32_t)((arr ? 1216 : 576) + n * 20 + sg * 4);
    }

    float acc[4][4];
#pragma unroll
    for (int j = 0; j < 4; j++)
#pragma unroll
        for (int i = 0; i < 4; i++) acc[j][i] = 0.0f;

    // prologue: chunks 0,1 into slots 0,1
#pragma unroll
    for (int p = 0; p < 2; p++) {
        uint32_t bo = wbase + (uint32_t)p * (WSLOT * 4);
#pragma unroll
        for (int j = 0; j < 4; j++) CP16(bo + sAo[j], gA[j] + p * 32);
#pragma unroll
        for (int j = 0; j < 8; j++) CP16(bo + sBo[j], gB[j] + p * 16);
        CP_COMMIT();
    }

    int slotc = 0, slotp = 2;
    for (int ch = 0; ch < NCHUNK; ch++) {
        CP_WAIT1();          // this lane's chunk-ch group complete
        __syncwarp();        // all lanes of warp past their waits
        if (ch + 2 < NCHUNK) {
            uint32_t bo = wbase + (uint32_t)slotp * (WSLOT * 4);
            int ko = (ch + 2) * 32, kw = (ch + 2) * 16;
#pragma unroll
            for (int j = 0; j < 4; j++) CP16(bo + sAo[j], gA[j] + ko);
#pragma unroll
            for (int j = 0; j < 8; j++) CP16(bo + sBo[j], gB[j] + kw);
        }
        CP_COMMIT();         // empty at tail keeps counts consistent
        if (++slotp == WRING) slotp = 0;

        const uint32_t* sb = wbuf + slotc * WSLOT;
        if (++slotc == WRING) slotc = 0;
        const float* sbf = (const float*)sb;
#pragma unroll
        for (int s = 0; s < 2; s++) {
            const int ab = s * 16 + 2 * t4;
            float2 v00 = *reinterpret_cast<const float2*>(sbf + ab + gid * 36);
            float2 v10 = *reinterpret_cast<const float2*>(sbf + ab + (gid + 8) * 36);
            float2 v01 = *reinterpret_cast<const float2*>(sbf + ab + 8 + gid * 36);
            float2 v11 = *reinterpret_cast<const float2*>(sbf + ab + 8 + (gid + 8) * 36);
            uint32_t ah0, ah1, ah2, ah3, al0, al1, al2, al3;
            split2t(v00, ah0, al0);
            split2t(v10, ah1, al1);
            split2t(v01, ah2, al2);
            split2t(v11, ah3, al3);
#pragma unroll
            for (int j = 0; j < 4; j++) {
                const int bx = 576 + (gid + 8 * j) * 20 + s * 8 + t4;
                uint32_t bh0 = sb[bx], bh1 = sb[bx + 4];
                uint32_t bl0 = sb[bx + 640], bl1 = sb[bx + 644];
                mma_bf16(acc[j][0], acc[j][1], acc[j][2], acc[j][3],
                         ah0, ah1, ah2, ah3, bh0, bh1);
                mma_bf16(acc[j][0], acc[j][1], acc[j][2], acc[j][3],
                         ah0, ah1, ah2, ah3, bl0, bl1);
                mma_bf16(acc[j][0], acc[j][1], acc[j][2], acc[j][3],
                         al0, al1, al2, al3, bh0, bh1);
            }
        }
    }
    __syncthreads();   // only barrier: before cross-half merge

    // ---- epilogue: add K-halves (fixed order), write logits, colmax ----
    float* red = (float*)smu;   // overlay [64][33]
    const int m0 = mt * 16;
    if (half == 1) {
#pragma unroll
        for (int j = 0; j < 4; j++) {
            int r0 = m0 + gid, c = 8 * j + 2 * t4;
            red[r0 * 33 + c]           = acc[j][0];
            red[r0 * 33 + c + 1]       = acc[j][1];
            red[(r0 + 8) * 33 + c]     = acc[j][2];
            red[(r0 + 8) * 33 + c + 1] = acc[j][3];
        }
    }
    __syncthreads();
    if (half == 0) {
#pragma unroll
        for (int j = 0; j < 4; j++) {
            int r0 = m0 + gid, c = 8 * j + 2 * t4;
            float v0 = acc[j][0] + red[r0 * 33 + c];
            float v1 = acc[j][1] + red[r0 * 33 + c + 1];
            float v2 = acc[j][2] + red[(r0 + 8) * 33 + c];
            float v3 = acc[j][3] + red[(r0 + 8) * 33 + c + 1];
            *reinterpret_cast<float2*>(&g_logits[(size_t)(rb + r0) * DOUT + c]) =
                make_float2(v0, v1);
            *reinterpret_cast<float2*>(&g_logits[(size_t)(rb + r0 + 8) * DOUT + c]) =
                make_float2(v2, v3);
            atomicMax(&smax[c],     fkey(fmaxf(v0, v2)));
            atomicMax(&smax[c + 1], fkey(fmaxf(v1, v3)));
        }
    }
    __syncthreads();
    if (t < DOUT) atomicMax(&g_colmax_bits[t], smax[t]);
}

// ---------------------------------------------------------------------------
// gemm1: support = X @ W -> pre-split, pre-transposed bf16 hi/lo.
// ---------------------------------------------------------------------------
#define ABUF_STRIDE (32 * 65)
#define SBUF_BASE   (8 * ABUF_STRIDE)
#define GEMM1_SMEM  ((SBUF_BASE + 8 * 32 * 32) * 4)

__global__ void __launch_bounds__(256)
gemm1_kernel(const float* __restrict__ A, const float* __restrict__ S)
{
    extern __shared__ float smem[];
    const int t = threadIdx.x, w = t >> 5, l = t & 31;
    const int rb = blockIdx.x * 64;
    const int K = DIN;

    if (blockIdx.x == 0 && t < DOUT) g_colmax_bits[t] = 0u;

    float* a_buf = smem + w * ABUF_STRIDE;
    float* s_buf = smem + SBUF_BASE + w * (32 * 32);
    const int kc = w * 32;

    unsigned long long acc0[16], acc1[16];
#pragma unroll
    for (int i = 0; i < 16; i++) { acc0[i] = 0ull; acc1[i] = 0ull; }

#pragma unroll
    for (int j = 0; j < 16; j++) {
        int f = j * 32 + l, row = f >> 3, k4 = (f & 7) << 2;
        float4 v = *reinterpret_cast<const float4*>(
            A + (size_t)(rb + row) * K + kc + k4);
        a_buf[(k4 + 0) * 65 + row] = v.x;
        a_buf[(k4 + 1) * 65 + row] = v.y;
        a_buf[(k4 + 2) * 65 + row] = v.z;
        a_buf[(k4 + 3) * 65 + row] = v.w;
    }
#pragma unroll
    for (int j = 0; j < 8; j++) {
        int f = j * 32 + l;
        *reinterpret_cast<float4*>(s_buf + f * 4) =
            *reinterpret_cast<const float4*>(S + (size_t)kc * 32 + f * 4);
    }
    __syncwarp();
#pragma unroll 4
    for (int k = 0; k < 32; k++) {
        unsigned long long a0 = pack2(a_buf[k * 65 + l]);
        unsigned long long a1 = pack2(a_buf[k * 65 + l + 32]);
        const ulonglong2* s2 = reinterpret_cast<const ulonglong2*>(s_buf + k * 32);
#pragma unroll
        for (int c = 0; c < 8; c++) {
            ulonglong2 sv = s2[c];
            acc0[2 * c]     = ffma2(a0, sv.x, acc0[2 * c]);
            acc0[2 * c + 1] = ffma2(a0, sv.y, acc0[2 * c + 1]);
            acc1[2 * c]     = ffma2(a1, sv.x, acc1[2 * c]);
            acc1[2 * c + 1] = ffma2(a1, sv.y, acc1[2 * c + 1]);
        }
    }

    __syncthreads();
    float* red = smem;
#pragma unroll
    for (int c = 0; c < 16; c++) {
        float2 v0 = unpack2(acc0[c]);
        float2 v1 = unpack2(acc1[c]);
        red[(w * 64 + l) * 33 + 2 * c]          = v0.x;
        red[(w * 64 + l) * 33 + 2 * c + 1]      = v0.y;
        red[(w * 64 + l + 32) * 33 + 2 * c]     = v1.x;
        red[(w * 64 + l + 32) * 33 + 2 * c + 1] = v1.y;
    }
    __syncthreads();
    {
        int row = t >> 2, c0 = (t & 3) * 8;
        float r[8];
#pragma unroll
        for (int i = 0; i < 8; i++) r[i] = 0.0f;
#pragma unroll
        for (int ww = 0; ww < 8; ww++) {
            const float* p = red + (ww * 64 + row) * 33 + c0;
#pragma unroll
            for (int i = 0; i < 8; i++) r[i] += p[i];
        }
#pragma unroll
        for (int i = 0; i < 8; i++) {
            __nv_bfloat16 hi = __float2bfloat16(r[i]);
            g_Bhi[(size_t)(c0 + i) * NN + rb + row] = hi;
            g_Blo[(size_t)(c0 + i) * NN + rb + row] =
                __float2bfloat16(r[i] - __bfloat162float(hi));
        }
    }
}

// ---------------------------------------------------------------------------
// pool: 64-row blocks x d-split (256 CTAs x 128 thr), fused exp-sum partials.
// ---------------------------------------------------------------------------
__global__ void __launch_bounds__(128, 4)
pool_kernel(const float* __restrict__ X)
{
    __shared__ float wsm[64 * DOUT];
    __shared__ float cmax[DOUT];
    const int t   = threadIdx.x;
    const int blk = (int)blockIdx.x >> 1;
    const int dh  = (int)blockIdx.x & 1;
    const int rb  = blk * 64;
    const int d   = dh * 128 + t;

    if (t < DOUT) cmax[t] = funkey(g_colmax_bits[t]);
    __syncthreads();
#pragma unroll
    for (int q = 0; q < 16; q++) {
        int idx = t * 16 + q, il = idx >> 5, c = idx & 31;
        wsm[idx] = __expf(g_logits[(size_t)(rb + il) * DOUT + c] - cmax[c]);
    }
    __syncthreads();

    if (dh == 0 && t < DOUT) {
        float s = 0.f;
#pragma unroll 8
        for (int il = 0; il < 64; il++) s += wsm[il * DOUT + t];
        g_sumpart[blk * DOUT + t] = s;
    }

    unsigned long long acc[16];
#pragma unroll
    for (int i = 0; i < 16; i++) acc[i] = 0ull;
    for (int g = 0; g < 8; g++) {
        float xv[8];
#pragma unroll
        for (int q = 0; q < 8; q++)
            xv[q] = X[(size_t)(rb + g * 8 + q) * DIN + d];
#pragma unroll
        for (int q = 0; q < 8; q++) {
            unsigned long long xp = pack2(xv[q]);
            const ulonglong2* wv =
                reinterpret_cast<const ulonglong2*>(wsm + (g * 8 + q) * DOUT);
#pragma unroll
            for (int c = 0; c < 8; c++) {
                ulonglong2 sv = wv[c];
                acc[2 * c]     = ffma2(xp, sv.x, acc[2 * c]);
                acc[2 * c + 1] = ffma2(xp, sv.y, acc[2 * c + 1]);
            }
        }
    }
    float* pp = g_part + (size_t)blk * (DOUT * DIN);
#pragma unroll
    for (int c = 0; c < 16; c++) {
        float2 v = unpack2(acc[c]);
        pp[(2 * c) * DIN + d]     = v.x;
        pp[(2 * c + 1) * DIN + d] = v.y;
    }
}

// ---------------------------------------------------------------------------
// reduce_out: 256 CTAs = 32 cols x 8 d-slices of 32.
// ---------------------------------------------------------------------------
__global__ void __launch_bounds__(256, 4)
reduce_out_kernel(float* __restrict__ out)
{
    __shared__ float s1[64];
    __shared__ float red2[8 * 32];
    const int c  = (int)blockIdx.x >> 3;
    const int d0 = ((int)blockIdx.x & 7) * 32;
    const int t  = threadIdx.x;

    if (t < 64)
        s1[t] = g_sumpart[t * DOUT + c] + g_sumpart[(t + 64) * DOUT + c];
    __syncthreads();
    for (int s = 32; s > 0; s >>= 1) {
        if (t < s) s1[t] += s1[t + s];
        __syncthreads();
    }
    const float inv = 1.0f / s1[0];

    const int sub = t >> 5, j = t & 31;
    float s = 0.0f;
    const float* base = g_part + (size_t)c * DIN + d0 + j;
#pragma unroll 8
    for (int i = 0; i < 16; i++)
        s += base[(size_t)(sub + 8 * i) * (DOUT * DIN)];
    red2[sub * 32 + j] = s;
    __syncthreads();
    if (t < 32) {
        float r = 0.0f;
#pragma unroll
        for (int q = 0; q < 8; q++) r += red2[q * 32 + t];
        out[c * DIN + d0 + t] = r * inv;
    }
}

extern "C" void kernel_launch(void* const* d_in, const int* in_sizes, int n_in,
                              void* d_out, int out_size)
{
    const float* X = (const float*)d_in[0];
    const float* A = (const float*)d_in[1];
    const float* W = (const float*)d_in[2];
    // d_in[3] = b: per-column constant -> softmax(axis 0) invariant -> dropped
    float* out = (float*)d_out;

    cudaFuncSetAttribute(gemm1_kernel,
                         cudaFuncAttributeMaxDynamicSharedMemorySize, GEMM1_SMEM);
    cudaFuncSetAttribute(gemm2_kernel,
                         cudaFuncAttributeMaxDynamicSharedMemorySize, GEMM2_SMEM);

    gemm1_kernel<<<NN / 64, 256, GEMM1_SMEM>>>(X, W);
    gemm2_kernel<<<NN / 64, 256, GEMM2_SMEM>>>(A);
    pool_kernel<<<NPART * 2, 128>>>(X);
    reduce_out_kernel<<<DOUT * 8, 256>>>(out);
}

// round 16
// speedup vs baseline: 1.3407x; 1.3407x over previous
#include <cuda_runtime.h>
#include <cuda_bf16.h>
#include <cstdint>

#define NN 8192
#define DIN 256
#define DOUT 32
#define NPART 128            // pool partial blocks (64 rows each)
#define NCHUNK 128

__device__ __align__(16) __nv_bfloat16 g_Bhi[DOUT * NN];
__device__ __align__(16) __nv_bfloat16 g_Blo[DOUT * NN];
__device__ float    g_logits[NN * DOUT];
__device__ unsigned g_colmax_bits[DOUT];
__device__ float    g_sumpart[NPART * DOUT];
__device__ float    g_part[NPART * DOUT * DIN];

// ---------------- helpers ----------------
__device__ __forceinline__ unsigned long long pack2(float x) {
    unsigned long long r; asm("mov.b64 %0, {%1, %1};" : "=l"(r) : "f"(x)); return r;
}
__device__ __forceinline__ unsigned long long ffma2(unsigned long long a,
                                                    unsigned long long b,
                                                    unsigned long long c) {
    unsigned long long d;
    asm("fma.rn.f32x2 %0, %1, %2, %3;" : "=l"(d) : "l"(a), "l"(b), "l"(c));
    return d;
}
__device__ __forceinline__ float2 unpack2(unsigned long long v) {
    float2 f; asm("mov.b64 {%0, %1}, %2;" : "=f"(f.x), "=f"(f.y) : "l"(v)); return f;
}
__device__ __forceinline__ unsigned fkey(float f) {
    int b = __float_as_int(f);
    return (unsigned)(b ^ ((b >> 31) | 0x80000000));
}
__device__ __forceinline__ float funkey(unsigned u) {
    int b = (u & 0x80000000u) ? (int)(u ^ 0x80000000u) : ~(int)u;
    return __int_as_float(b);
}
__device__ __forceinline__ void split2t(float2 v, uint32_t& hi, uint32_t& lo) {
    uint32_t u0 = __float_as_uint(v.x), u1 = __float_as_uint(v.y);
    asm("prmt.b32 %0, %1, %2, 0x7632;" : "=r"(hi) : "r"(u0), "r"(u1));
    float l0 = v.x - __uint_as_float(u0 & 0xFFFF0000u);
    float l1 = v.y - __uint_as_float(u1 & 0xFFFF0000u);
    asm("cvt.rn.bf16x2.f32 %0, %1, %2;" : "=r"(lo) : "f"(l1), "f"(l0));
}
__device__ __forceinline__ uint32_t smem_u32(const void* p) {
    uint32_t a;
    asm("{ .reg .u64 t; cvta.to.shared.u64 t, %1; cvt.u32.u64 %0, t; }"
        : "=r"(a) : "l"(p));
    return a;
}
__device__ __forceinline__ void mma_bf16(float& c0, float& c1, float& c2, float& c3,
                                         uint32_t a0, uint32_t a1, uint32_t a2,
                                         uint32_t a3, uint32_t b0, uint32_t b1) {
    asm volatile(
        "mma.sync.aligned.m16n8k16.row.col.f32.bf16.bf16.f32 "
        "{%0,%1,%2,%3}, {%4,%5,%6,%7}, {%8,%9}, {%0,%1,%2,%3};"
        : "+f"(c0), "+f"(c1), "+f"(c2), "+f"(c3)
        : "r"(a0), "r"(a1), "r"(a2), "r"(a3), "r"(b0), "r"(b1));
}
#define CP16(sm, gp) asm volatile( \
    "cp.async.cg.shared.global [%0], [%1], 16;" :: "r"(sm), "l"(gp) : "memory")
#define CP_COMMIT() asm volatile("cp.async.commit_group;" ::: "memory")
#define CP_WAIT5()  asm volatile("cp.async.wait_group 5;" ::: "memory")

// ---------------------------------------------------------------------------
// gemm2 (champion structure): 128 CTAs x 64 rows, 8 warps = 4 m16 x 2
// K-halves, cp.async 7-deep ring (wait_group 5 -> 6 chunks in flight),
// bf16 3-term with truncation split.
// ---------------------------------------------------------------------------
#define BUFW 7168
#define BHI_OFF 4608
#define BLO_OFF 5888
#define RING 7
#define GEMM2_SMEM (RING * BUFW * 4)     // 200704 B

__global__ void __launch_bounds__(256, 1)
gemm2_kernel(const float* __restrict__ A)
{
    extern __shared__ uint32_t smu[];
    __shared__ unsigned smax[DOUT];
    const int t = threadIdx.x;
    const int w = t >> 5, lane = t & 31;
    const int gid = lane >> 2, t4 = lane & 3;
    const int half = w >> 2, m0 = (w & 3) * 16;
    const int rb = blockIdx.x * 64;
    const uint32_t* __restrict__ BHg = (const uint32_t*)g_Bhi;
    const uint32_t* __restrict__ BLg = (const uint32_t*)g_Blo;
    const uint32_t smaddr = smem_u32(smu);

    if (t < DOUT) smax[t] = 0u;

    const float* gA[4]; uint32_t sA[4];
#pragma unroll
    for (int j = 0; j < 4; j++) {
        int f = t + j * 256;
        int hf = f >> 9, r = (f >> 3) & 63, seg = f & 7;
        gA[j] = A + (size_t)(rb + r) * NN + hf * 4096 + seg * 4;
        sA[j] = smaddr + 4u * (hf * 2304 + r * 36 + seg * 4);
    }
    const uint32_t* gB[2]; uint32_t sB[2];
#pragma unroll
    for (int j = 0; j < 2; j++) {
        int f = t + j * 256;
        int arr = f >> 8, rem = f & 255;
        int hs = rem >> 7, ns = (rem >> 2) & 31, sg = rem & 3;
        gB[j] = (arr ? BLg : BHg) + ns * 4096 + hs * 2048 + sg * 4;
        sB[j] = smaddr + 4u * ((arr ? BLO_OFF : BHI_OFF) + hs * 640 + ns * 20 + sg * 4);
    }

    float acc[4][4];
#pragma unroll
    for (int j = 0; j < 4; j++)
#pragma unroll
        for (int i = 0; i < 4; i++) acc[j][i] = 0.0f;

    // prologue: chunks 0..5 into buffers 0..5
#pragma unroll
    for (int p = 0; p < 6; p++) {
        uint32_t bo = (uint32_t)p * (BUFW * 4);
#pragma unroll
        for (int j = 0; j < 4; j++) CP16(sA[j] + bo, gA[j] + p * 32);
#pragma unroll
        for (int j = 0; j < 2; j++) CP16(sB[j] + bo, gB[j] + p * 16);
        CP_COMMIT();
    }

    int bufc = 0, bufp = 6;
    for (int ch = 0; ch < NCHUNK; ch++) {
        CP_WAIT5();
        __syncthreads();
        if (ch + 6 < NCHUNK) {
            uint32_t bo = (uint32_t)bufp * (BUFW * 4);
            int ko = (ch + 6) * 32, kw = (ch + 6) * 16;
#pragma unroll
            for (int j = 0; j < 4; j++) CP16(sA[j] + bo, gA[j] + ko);
#pragma unroll
            for (int j = 0; j < 2; j++) CP16(sB[j] + bo, gB[j] + kw);
        }
        CP_COMMIT();
        if (++bufp == RING) bufp = 0;

        const uint32_t* sb = smu + bufc * BUFW;
        if (++bufc == RING) bufc = 0;
        const float* sbf = (const float*)sb;
#pragma unroll
        for (int s = 0; s < 2; s++) {
            const int ab = half * 2304 + s * 16 + 2 * t4;
            float2 v00 = *reinterpret_cast<const float2*>(sbf + ab + (m0 + gid) * 36);
            float2 v10 = *reinterpret_cast<const float2*>(sbf + ab + (m0 + gid + 8) * 36);
            float2 v01 = *reinterpret_cast<const float2*>(sbf + ab + 8 + (m0 + gid) * 36);
            float2 v11 = *reinterpret_cast<const float2*>(sbf + ab + 8 + (m0 + gid + 8) * 36);
            uint32_t ah0, ah1, ah2, ah3, al0, al1, al2, al3;
            split2t(v00, ah0, al0);
            split2t(v10, ah1, al1);
            split2t(v01, ah2, al2);
            split2t(v11, ah3, al3);
#pragma unroll
            for (int j = 0; j < 4; j++) {
                const int bx = BHI_OFF + half * 640 + (gid + 8 * j) * 20 + s * 8 + t4;
                uint32_t bh0 = sb[bx], bh1 = sb[bx + 4];
                uint32_t bl0 = sb[bx + (BLO_OFF - BHI_OFF)];
                uint32_t bl1 = sb[bx + (BLO_OFF - BHI_OFF) + 4];
                mma_bf16(acc[j][0], acc[j][1], acc[j][2], acc[j][3],
                         ah0, ah1, ah2, ah3, bh0, bh1);
                mma_bf16(acc[j][0], acc[j][1], acc[j][2], acc[j][3],
                         ah0, ah1, ah2, ah3, bl0, bl1);
                mma_bf16(acc[j][0], acc[j][1], acc[j][2], acc[j][3],
                         al0, al1, al2, al3, bh0, bh1);
            }
        }
    }
    __syncthreads();

    float* red = (float*)smu;   // overlay [64][33]
    if (half == 1) {
#pragma unroll
        for (int j = 0; j < 4; j++) {
            int r0 = m0 + gid, c = 8 * j + 2 * t4;
            red[r0 * 33 + c]           = acc[j][0];
            red[r0 * 33 + c + 1]       = acc[j][1];
            red[(r0 + 8) * 33 + c]     = acc[j][2];
            red[(r0 + 8) * 33 + c + 1] = acc[j][3];
        }
    }
    __syncthreads();
    if (half == 0) {
#pragma unroll
        for (int j = 0; j < 4; j++) {
            int r0 = m0 + gid, c = 8 * j + 2 * t4;
            float v0 = acc[j][0] + red[r0 * 33 + c];
            float v1 = acc[j][1] + red[r0 * 33 + c + 1];
            float v2 = acc[j][2] + red[(r0 + 8) * 33 + c];
            float v3 = acc[j][3] + red[(r0 + 8) * 33 + c + 1];
            *reinterpret_cast<float2*>(&g_logits[(size_t)(rb + r0) * DOUT + c]) =
                make_float2(v0, v1);
            *reinterpret_cast<float2*>(&g_logits[(size_t)(rb + r0 + 8) * DOUT + c]) =
                make_float2(v2, v3);
            atomicMax(&smax[c],     fkey(fmaxf(v0, v2)));
            atomicMax(&smax[c + 1], fkey(fmaxf(v1, v3)));
        }
    }
    __syncthreads();
    if (t < DOUT) atomicMax(&g_colmax_bits[t], smax[t]);
}

// ---------------------------------------------------------------------------
// gemm1: support = X @ W -> pre-split, pre-transposed bf16 hi/lo.
// ---------------------------------------------------------------------------
#define ABUF_STRIDE (32 * 65)
#define SBUF_BASE   (8 * ABUF_STRIDE)
#define GEMM1_SMEM  ((SBUF_BASE + 8 * 32 * 32) * 4)

__global__ void __launch_bounds__(256)
gemm1_kernel(const float* __restrict__ A, const float* __restrict__ S)
{
    extern __shared__ float smem[];
    const int t = threadIdx.x, w = t >> 5, l = t & 31;
    const int rb = blockIdx.x * 64;
    const int K = DIN;

    if (blockIdx.x == 0 && t < DOUT) g_colmax_bits[t] = 0u;

    float* a_buf = smem + w * ABUF_STRIDE;
    float* s_buf = smem + SBUF_BASE + w * (32 * 32);
    const int kc = w * 32;

    unsigned long long acc0[16], acc1[16];
#pragma unroll
    for (int i = 0; i < 16; i++) { acc0[i] = 0ull; acc1[i] = 0ull; }

#pragma unroll
    for (int j = 0; j < 16; j++) {
        int f = j * 32 + l, row = f >> 3, k4 = (f & 7) << 2;
        float4 v = *reinterpret_cast<const float4*>(
            A + (size_t)(rb + row) * K + kc + k4);
        a_buf[(k4 + 0) * 65 + row] = v.x;
        a_buf[(k4 + 1) * 65 + row] = v.y;
        a_buf[(k4 + 2) * 65 + row] = v.z;
        a_buf[(k4 + 3) * 65 + row] = v.w;
    }
#pragma unroll
    for (int j = 0; j < 8; j++) {
        int f = j * 32 + l;
        *reinterpret_cast<float4*>(s_buf + f * 4) =
            *reinterpret_cast<const float4*>(S + (size_t)kc * 32 + f * 4);
    }
    __syncwarp();
#pragma unroll 4
    for (int k = 0; k < 32; k++) {
        unsigned long long a0 = pack2(a_buf[k * 65 + l]);
        unsigned long long a1 = pack2(a_buf[k * 65 + l + 32]);
        const ulonglong2* s2 = reinterpret_cast<const ulonglong2*>(s_buf + k * 32);
#pragma unroll
        for (int c = 0; c < 8; c++) {
            ulonglong2 sv = s2[c];
            acc0[2 * c]     = ffma2(a0, sv.x, acc0[2 * c]);
            acc0[2 * c + 1] = ffma2(a0, sv.y, acc0[2 * c + 1]);
            acc1[2 * c]     = ffma2(a1, sv.x, acc1[2 * c]);
            acc1[2 * c + 1] = ffma2(a1, sv.y, acc1[2 * c + 1]);
        }
    }

    __syncthreads();
    float* red = smem;
#pragma unroll
    for (int c = 0; c < 16; c++) {
        float2 v0 = unpack2(acc0[c]);
        float2 v1 = unpack2(acc1[c]);
        red[(w * 64 + l) * 33 + 2 * c]          = v0.x;
        red[(w * 64 + l) * 33 + 2 * c + 1]      = v0.y;
        red[(w * 64 + l + 32) * 33 + 2 * c]     = v1.x;
        red[(w * 64 + l + 32) * 33 + 2 * c + 1] = v1.y;
    }
    __syncthreads();
    {
        int row = t >> 2, c0 = (t & 3) * 8;
        float r[8];
#pragma unroll
        for (int i = 0; i < 8; i++) r[i] = 0.0f;
#pragma unroll
        for (int ww = 0; ww < 8; ww++) {
            const float* p = red + (ww * 64 + row) * 33 + c0;
#pragma unroll
            for (int i = 0; i < 8; i++) r[i] += p[i];
        }
#pragma unroll
        for (int i = 0; i < 8; i++) {
            __nv_bfloat16 hi = __float2bfloat16(r[i]);
            g_Bhi[(size_t)(c0 + i) * NN + rb + row] = hi;
            g_Blo[(size_t)(c0 + i) * NN + rb + row] =
                __float2bfloat16(r[i] - __bfloat162float(hi));
        }
    }
}

// ---------------------------------------------------------------------------
// pool: 64-row blocks x d-split (256 CTAs x 128 thr), fused exp-sum partials.
// ---------------------------------------------------------------------------
__global__ void __launch_bounds__(128, 4)
pool_kernel(const float* __restrict__ X)
{
    __shared__ float wsm[64 * DOUT];
    __shared__ float cmax[DOUT];
    const int t   = threadIdx.x;
    const int blk = (int)blockIdx.x >> 1;
    const int dh  = (int)blockIdx.x & 1;
    const int rb  = blk * 64;
    const int d   = dh * 128 + t;

    if (t < DOUT) cmax[t] = funkey(g_colmax_bits[t]);
    __syncthreads();
#pragma unroll
    for (int q = 0; q < 16; q++) {
        int idx = t * 16 + q, il = idx >> 5, c = idx & 31;
        wsm[idx] = __expf(g_logits[(size_t)(rb + il) * DOUT + c] - cmax[c]);
    }
    __syncthreads();

    if (dh == 0 && t < DOUT) {
        float s = 0.f;
#pragma unroll 8
        for (int il = 0; il < 64; il++) s += wsm[il * DOUT + t];
        g_sumpart[blk * DOUT + t] = s;
    }

    unsigned long long acc[16];
#pragma unroll
    for (int i = 0; i < 16; i++) acc[i] = 0ull;
    for (int g = 0; g < 8; g++) {
        float xv[8];
#pragma unroll
        for (int q = 0; q < 8; q++)
            xv[q] = X[(size_t)(rb + g * 8 + q) * DIN + d];
#pragma unroll
        for (int q = 0; q < 8; q++) {
            unsigned long long xp = pack2(xv[q]);
            const ulonglong2* wv =
                reinterpret_cast<const ulonglong2*>(wsm + (g * 8 + q) * DOUT);
#pragma unroll
            for (int c = 0; c < 8; c++) {
                ulonglong2 sv = wv[c];
                acc[2 * c]     = ffma2(xp, sv.x, acc[2 * c]);
                acc[2 * c + 1] = ffma2(xp, sv.y, acc[2 * c + 1]);
            }
        }
    }
    float* pp = g_part + (size_t)blk * (DOUT * DIN);
#pragma unroll
    for (int c = 0; c < 16; c++) {
        float2 v = unpack2(acc[c]);
        pp[(2 * c) * DIN + d]     = v.x;
        pp[(2 * c + 1) * DIN + d] = v.y;
    }
}

// ---------------------------------------------------------------------------
// reduce_out: 256 CTAs = 32 cols x 8 d-slices of 32.
// ---------------------------------------------------------------------------
__global__ void __launch_bounds__(256, 4)
reduce_out_kernel(float* __restrict__ out)
{
    __shared__ float s1[64];
    __shared__ float red2[8 * 32];
    const int c  = (int)blockIdx.x >> 3;
    const int d0 = ((int)blockIdx.x & 7) * 32;
    const int t  = threadIdx.x;

    if (t < 64)
        s1[t] = g_sumpart[t * DOUT + c] + g_sumpart[(t + 64) * DOUT + c];
    __syncthreads();
    for (int s = 32; s > 0; s >>= 1) {
        if (t < s) s1[t] += s1[t + s];
        __syncthreads();
    }
    const float inv = 1.0f / s1[0];

    const int sub = t >> 5, j = t & 31;
    float s = 0.0f;
    const float* base = g_part + (size_t)c * DIN + d0 + j;
#pragma unroll 8
    for (int i = 0; i < 16; i++)
        s += base[(size_t)(sub + 8 * i) * (DOUT * DIN)];
    red2[sub * 32 + j] = s;
    __syncthreads();
    if (t < 32) {
        float r = 0.0f;
#pragma unroll
        for (int q = 0; q < 8; q++) r += red2[q * 32 + t];
        out[c * DIN + d0 + t] = r * inv;
    }
}

extern "C" void kernel_launch(void* const* d_in, const int* in_sizes, int n_in,
                              void* d_out, int out_size)
{
    const float* X = (const float*)d_in[0];
    const float* A = (const float*)d_in[1];
    const float* W = (const float*)d_in[2];
    // d_in[3] = b: per-column constant -> softmax(axis 0) invariant -> dropped
    float* out = (float*)d_out;

    cudaFuncSetAttribute(gemm1_kernel,
                         cudaFuncAttributeMaxDynamicSharedMemorySize, GEMM1_SMEM);
    cudaFuncSetAttribute(gemm2_kernel,
                         cudaFuncAttributeMaxDynamicSharedMemorySize, GEMM2_SMEM);

    gemm1_kernel<<<NN / 64, 256, GEMM1_SMEM>>>(X, W);
    gemm2_kernel<<<NN / 64, 256, GEMM2_SMEM>>>(A);
    pool_kernel<<<NPART * 2, 128>>>(X);
    reduce_out_kernel<<<DOUT * 8, 256>>>(out);
}

// round 17
// speedup vs baseline: 1.3496x; 1.0066x over previous
#include <cuda_runtime.h>
#include <cuda_bf16.h>
#include <cstdint>

#define NN 8192
#define DIN 256
#define DOUT 32
#define NPART 128            // partial blocks (64 rows each) == gemm2 CTAs
#define NCHUNK 128

__device__ __align__(16) __nv_bfloat16 g_Bhi[DOUT * NN];
__device__ __align__(16) __nv_bfloat16 g_Blo[DOUT * NN];
__device__ float    g_blockmax[NPART * DOUT];   // per-block column max
__device__ float    g_sumpart[NPART * DOUT];    // per-block exp sums (local max)
__device__ float    g_part[NPART * DOUT * DIN]; // per-block pool partials

// ---------------- helpers ----------------
__device__ __forceinline__ unsigned long long pack2(float x) {
    unsigned long long r; asm("mov.b64 %0, {%1, %1};" : "=l"(r) : "f"(x)); return r;
}
__device__ __forceinline__ unsigned long long ffma2(unsigned long long a,
                                                    unsigned long long b,
                                                    unsigned long long c) {
    unsigned long long d;
    asm("fma.rn.f32x2 %0, %1, %2, %3;" : "=l"(d) : "l"(a), "l"(b), "l"(c));
    return d;
}
__device__ __forceinline__ float2 unpack2(unsigned long long v) {
    float2 f; asm("mov.b64 {%0, %1}, %2;" : "=f"(f.x), "=f"(f.y) : "l"(v)); return f;
}
__device__ __forceinline__ unsigned fkey(float f) {
    int b = __float_as_int(f);
    return (unsigned)(b ^ ((b >> 31) | 0x80000000));
}
__device__ __forceinline__ float funkey(unsigned u) {
    int b = (u & 0x80000000u) ? (int)(u ^ 0x80000000u) : ~(int)u;
    return __int_as_float(b);
}
__device__ __forceinline__ void split2t(float2 v, uint32_t& hi, uint32_t& lo) {
    uint32_t u0 = __float_as_uint(v.x), u1 = __float_as_uint(v.y);
    asm("prmt.b32 %0, %1, %2, 0x7632;" : "=r"(hi) : "r"(u0), "r"(u1));
    float l0 = v.x - __uint_as_float(u0 & 0xFFFF0000u);
    float l1 = v.y - __uint_as_float(u1 & 0xFFFF0000u);
    asm("cvt.rn.bf16x2.f32 %0, %1, %2;" : "=r"(lo) : "f"(l1), "f"(l0));
}
__device__ __forceinline__ uint32_t smem_u32(const void* p) {
    uint32_t a;
    asm("{ .reg .u64 t; cvta.to.shared.u64 t, %1; cvt.u32.u64 %0, t; }"
        : "=r"(a) : "l"(p));
    return a;
}
__device__ __forceinline__ void mma_bf16(float& c0, float& c1, float& c2, float& c3,
                                         uint32_t a0, uint32_t a1, uint32_t a2,
                                         uint32_t a3, uint32_t b0, uint32_t b1) {
    asm volatile(
        "mma.sync.aligned.m16n8k16.row.col.f32.bf16.bf16.f32 "
        "{%0,%1,%2,%3}, {%4,%5,%6,%7}, {%8,%9}, {%0,%1,%2,%3};"
        : "+f"(c0), "+f"(c1), "+f"(c2), "+f"(c3)
        : "r"(a0), "r"(a1), "r"(a2), "r"(a3), "r"(b0), "r"(b1));
}
#define CP16(sm, gp) asm volatile( \
    "cp.async.cg.shared.global [%0], [%1], 16;" :: "r"(sm), "l"(gp) : "memory")
#define CP_COMMIT() asm volatile("cp.async.commit_group;" ::: "memory")
#define CP_WAIT4()  asm volatile("cp.async.wait_group 4;" ::: "memory")

// ---------------------------------------------------------------------------
// gemm2+pool fused: 128 CTAs x 64 rows, 8 warps = 4 m16 x 2 K-halves,
// cp.async 6-deep ring, bf16 3-term. Epilogue keeps logits IN SMEM, takes the
// CTA-LOCAL column max, and runs the pooling for its own 64 rows inline
// (flash-softmax: reduce_out rescales blocks by exp(M_b - M) later).
// SMEM overlays after mainloop: red [0,2112) | logit_sm [2112,4224) |
// wsm [4224,6272) words.
// ---------------------------------------------------------------------------
#define BUFW 7168
#define BHI_OFF 4608
#define BLO_OFF 5888
#define RING 6
#define GEMM2_SMEM (RING * BUFW * 4)     // 172032 B

__global__ void __launch_bounds__(256, 1)
gemm2_kernel(const float* __restrict__ A, const float* __restrict__ X)
{
    extern __shared__ uint32_t smu[];
    __shared__ unsigned smax[DOUT];
    __shared__ float cm[DOUT];
    const int t = threadIdx.x;
    const int w = t >> 5, lane = t & 31;
    const int gid = lane >> 2, t4 = lane & 3;
    const int half = w >> 2, m0 = (w & 3) * 16;
    const int blk = blockIdx.x;
    const int rb = blk * 64;
    const uint32_t* __restrict__ BHg = (const uint32_t*)g_Bhi;
    const uint32_t* __restrict__ BLg = (const uint32_t*)g_Blo;
    const uint32_t smaddr = smem_u32(smu);

    if (t < DOUT) smax[t] = 0u;

    const float* gA[4]; uint32_t sA[4];
#pragma unroll
    for (int j = 0; j < 4; j++) {
        int f = t + j * 256;
        int hf = f >> 9, r = (f >> 3) & 63, seg = f & 7;
        gA[j] = A + (size_t)(rb + r) * NN + hf * 4096 + seg * 4;
        sA[j] = smaddr + 4u * (hf * 2304 + r * 36 + seg * 4);
    }
    const uint32_t* gB[2]; uint32_t sB[2];
#pragma unroll
    for (int j = 0; j < 2; j++) {
        int f = t + j * 256;
        int arr = f >> 8, rem = f & 255;
        int hs = rem >> 7, ns = (rem >> 2) & 31, sg = rem & 3;
        gB[j] = (arr ? BLg : BHg) + ns * 4096 + hs * 2048 + sg * 4;
        sB[j] = smaddr + 4u * ((arr ? BLO_OFF : BHI_OFF) + hs * 640 + ns * 20 + sg * 4);
    }

    float acc[4][4];
#pragma unroll
    for (int j = 0; j < 4; j++)
#pragma unroll
        for (int i = 0; i < 4; i++) acc[j][i] = 0.0f;

#pragma unroll
    for (int p = 0; p < 5; p++) {
        uint32_t bo = (uint32_t)p * (BUFW * 4);
#pragma unroll
        for (int j = 0; j < 4; j++) CP16(sA[j] + bo, gA[j] + p * 32);
#pragma unroll
        for (int j = 0; j < 2; j++) CP16(sB[j] + bo, gB[j] + p * 16);
        CP_COMMIT();
    }

    int bufc = 0, bufp = 5;
    for (int ch = 0; ch < NCHUNK; ch++) {
        CP_WAIT4();
        __syncthreads();
        if (ch + 5 < NCHUNK) {
            uint32_t bo = (uint32_t)bufp * (BUFW * 4);
            int ko = (ch + 5) * 32, kw = (ch + 5) * 16;
#pragma unroll
            for (int j = 0; j < 4; j++) CP16(sA[j] + bo, gA[j] + ko);
#pragma unroll
            for (int j = 0; j < 2; j++) CP16(sB[j] + bo, gB[j] + kw);
        }
        CP_COMMIT();
        if (++bufp == RING) bufp = 0;

        const uint32_t* sb = smu + bufc * BUFW;
        if (++bufc == RING) bufc = 0;
        const float* sbf = (const float*)sb;
#pragma unroll
        for (int s = 0; s < 2; s++) {
            const int ab = half * 2304 + s * 16 + 2 * t4;
            float2 v00 = *reinterpret_cast<const float2*>(sbf + ab + (m0 + gid) * 36);
            float2 v10 = *reinterpret_cast<const float2*>(sbf + ab + (m0 + gid + 8) * 36);
            float2 v01 = *reinterpret_cast<const float2*>(sbf + ab + 8 + (m0 + gid) * 36);
            float2 v11 = *reinterpret_cast<const float2*>(sbf + ab + 8 + (m0 + gid + 8) * 36);
            uint32_t ah0, ah1, ah2, ah3, al0, al1, al2, al3;
            split2t(v00, ah0, al0);
            split2t(v10, ah1, al1);
            split2t(v01, ah2, al2);
            split2t(v11, ah3, al3);
#pragma unroll
            for (int j = 0; j < 4; j++) {
                const int bx = BHI_OFF + half * 640 + (gid + 8 * j) * 20 + s * 8 + t4;
                uint32_t bh0 = sb[bx], bh1 = sb[bx + 4];
                uint32_t bl0 = sb[bx + (BLO_OFF - BHI_OFF)];
                uint32_t bl1 = sb[bx + (BLO_OFF - BHI_OFF) + 4];
                mma_bf16(acc[j][0], acc[j][1], acc[j][2], acc[j][3],
                         ah0, ah1, ah2, ah3, bh0, bh1);
                mma_bf16(acc[j][0], acc[j][1], acc[j][2], acc[j][3],
                         ah0, ah1, ah2, ah3, bl0, bl1);
                mma_bf16(acc[j][0], acc[j][1], acc[j][2], acc[j][3],
                         al0, al1, al2, al3, bh0, bh1);
            }
        }
    }
    __syncthreads();

    // ---- epilogue: merge K-halves (fixed order) into SMEM logits + local max
    float* red = (float*)smu;             // [64][33]
    float* lsm = (float*)(smu + 2112);    // [64][33] final logits
    float* wsm = (float*)(smu + 4224);    // [64][32] exp weights
    if (half == 1) {
#pragma unroll
        for (int j = 0; j < 4; j++) {
            int r0 = m0 + gid, c = 8 * j + 2 * t4;
            red[r0 * 33 + c]           = acc[j][0];
            red[r0 * 33 + c + 1]       = acc[j][1];
            red[(r0 + 8) * 33 + c]     = acc[j][2];
            red[(r0 + 8) * 33 + c + 1] = acc[j][3];
        }
    }
    __syncthreads();
    if (half == 0) {
#pragma unroll
        for (int j = 0; j < 4; j++) {
            int r0 = m0 + gid, c = 8 * j + 2 * t4;
            float v0 = acc[j][0] + red[r0 * 33 + c];
            float v1 = acc[j][1] + red[r0 * 33 + c + 1];
            float v2 = acc[j][2] + red[(r0 + 8) * 33 + c];
            float v3 = acc[j][3] + red[(r0 + 8) * 33 + c + 1];
            lsm[r0 * 33 + c]           = v0;
            lsm[r0 * 33 + c + 1]       = v1;
            lsm[(r0 + 8) * 33 + c]     = v2;
            lsm[(r0 + 8) * 33 + c + 1] = v3;
            atomicMax(&smax[c],     fkey(fmaxf(v0, v2)));
            atomicMax(&smax[c + 1], fkey(fmaxf(v1, v3)));
        }
    }
    __syncthreads();
    if (t < DOUT) {
        float m = funkey(smax[t]);
        cm[t] = m;
        g_blockmax[blk * DOUT + t] = m;   // per-block max for flash rescale
    }
    __syncthreads();

    // ---- local exp weights ----
#pragma unroll
    for (int q = 0; q < 8; q++) {
        int idx = t * 8 + q, il = idx >> 5, c = idx & 31;
        wsm[il * DOUT + c] = __expf(lsm[il * 33 + c] - cm[c]);
    }
    __syncthreads();

    // per-block exp sums
    if (t < DOUT) {
        float s = 0.f;
#pragma unroll 8
        for (int il = 0; il < 64; il++) s += wsm[il * DOUT + t];
        g_sumpart[blk * DOUT + t] = s;
    }

    // ---- inline pool: part[blk][c][d] = sum_i wsm[i][c] * X[i][d], d = t ----
    unsigned long long pacc[16];
#pragma unroll
    for (int i = 0; i < 16; i++) pacc[i] = 0ull;
    for (int g = 0; g < 8; g++) {
        float xv[8];
#pragma unroll
        for (int q = 0; q < 8; q++)
            xv[q] = X[(size_t)(rb + g * 8 + q) * DIN + t];
#pragma unroll
        for (int q = 0; q < 8; q++) {
            unsigned long long xp = pack2(xv[q]);
            const ulonglong2* wv =
                reinterpret_cast<const ulonglong2*>(wsm + (g * 8 + q) * DOUT);
#pragma unroll
            for (int c = 0; c < 8; c++) {
                ulonglong2 sv = wv[c];
                pacc[2 * c]     = ffma2(xp, sv.x, pacc[2 * c]);
                pacc[2 * c + 1] = ffma2(xp, sv.y, pacc[2 * c + 1]);
            }
        }
    }
    float* pp = g_part + (size_t)blk * (DOUT * DIN);
#pragma unroll
    for (int c = 0; c < 16; c++) {
        float2 v = unpack2(pacc[c]);
        pp[(2 * c) * DIN + t]     = v.x;
        pp[(2 * c + 1) * DIN + t] = v.y;
    }
}

// ---------------------------------------------------------------------------
// gemm1: support = X @ W -> pre-split, pre-transposed bf16 hi/lo.
// ---------------------------------------------------------------------------
#define ABUF_STRIDE (32 * 65)
#define SBUF_BASE   (8 * ABUF_STRIDE)
#define GEMM1_SMEM  ((SBUF_BASE + 8 * 32 * 32) * 4)

__global__ void __launch_bounds__(256)
gemm1_kernel(const float* __restrict__ A, const float* __restrict__ S)
{
    extern __shared__ float smem[];
    const int t = threadIdx.x, w = t >> 5, l = t & 31;
    const int rb = blockIdx.x * 64;
    const int K = DIN;

    float* a_buf = smem + w * ABUF_STRIDE;
    float* s_buf = smem + SBUF_BASE + w * (32 * 32);
    const int kc = w * 32;

    unsigned long long acc0[16], acc1[16];
#pragma unroll
    for (int i = 0; i < 16; i++) { acc0[i] = 0ull; acc1[i] = 0ull; }

#pragma unroll
    for (int j = 0; j < 16; j++) {
        int f = j * 32 + l, row = f >> 3, k4 = (f & 7) << 2;
        float4 v = *reinterpret_cast<const float4*>(
            A + (size_t)(rb + row) * K + kc + k4);
        a_buf[(k4 + 0) * 65 + row] = v.x;
        a_buf[(k4 + 1) * 65 + row] = v.y;
        a_buf[(k4 + 2) * 65 + row] = v.z;
        a_buf[(k4 + 3) * 65 + row] = v.w;
    }
#pragma unroll
    for (int j = 0; j < 8; j++) {
        int f = j * 32 + l;
        *reinterpret_cast<float4*>(s_buf + f * 4) =
            *reinterpret_cast<const float4*>(S + (size_t)kc * 32 + f * 4);
    }
    __syncwarp();
#pragma unroll 4
    for (int k = 0; k < 32; k++) {
        unsigned long long a0 = pack2(a_buf[k * 65 + l]);
        unsigned long long a1 = pack2(a_buf[k * 65 + l + 32]);
        const ulonglong2* s2 = reinterpret_cast<const ulonglong2*>(s_buf + k * 32);
#pragma unroll
        for (int c = 0; c < 8; c++) {
            ulonglong2 sv = s2[c];
            acc0[2 * c]     = ffma2(a0, sv.x, acc0[2 * c]);
            acc0[2 * c + 1] = ffma2(a0, sv.y, acc0[2 * c + 1]);
            acc1[2 * c]     = ffma2(a1, sv.x, acc1[2 * c]);
            acc1[2 * c + 1] = ffma2(a1, sv.y, acc1[2 * c + 1]);
        }
    }

    __syncthreads();
    float* red = smem;
#pragma unroll
    for (int c = 0; c < 16; c++) {
        float2 v0 = unpack2(acc0[c]);
        float2 v1 = unpack2(acc1[c]);
        red[(w * 64 + l) * 33 + 2 * c]          = v0.x;
        red[(w * 64 + l) * 33 + 2 * c + 1]      = v0.y;
        red[(w * 64 + l + 32) * 33 + 2 * c]     = v1.x;
        red[(w * 64 + l + 32) * 33 + 2 * c + 1] = v1.y;
    }
    __syncthreads();
    {
        int row = t >> 2, c0 = (t & 3) * 8;
        float r[8];
#pragma unroll
        for (int i = 0; i < 8; i++) r[i] = 0.0f;
#pragma unroll
        for (int ww = 0; ww < 8; ww++) {
            const float* p = red + (ww * 64 + row) * 33 + c0;
#pragma unroll
            for (int i = 0; i < 8; i++) r[i] += p[i];
        }
#pragma unroll
        for (int i = 0; i < 8; i++) {
            __nv_bfloat16 hi = __float2bfloat16(r[i]);
            g_Bhi[(size_t)(c0 + i) * NN + rb + row] = hi;
            g_Blo[(size_t)(c0 + i) * NN + rb + row] =
                __float2bfloat16(r[i] - __bfloat162float(hi));
        }
    }
}

// ---------------------------------------------------------------------------
// reduce_out: 256 CTAs = 32 cols x 8 d-slices. Flash-rescale merge:
//   M_c = max_b M_bc (tree); s_b = exp(M_bc - M_c)
//   out[c][d] = (sum_b s_b * part[b][c][d]) / (sum_b s_b * sumpart[b][c])
// All reductions fixed-order -> deterministic.
// ---------------------------------------------------------------------------
__global__ void __launch_bounds__(256, 4)
reduce_out_kernel(float* __restrict__ out)
{
    __shared__ float mred[128];
    __shared__ float sscale[128];
    __shared__ float dred[128];
    __shared__ float red2[8 * 32];
    const int c  = (int)blockIdx.x >> 3;
    const int d0 = ((int)blockIdx.x & 7) * 32;
    const int t  = threadIdx.x;

    // load per-block maxima, tree-max
    float mb = 0.0f;
    if (t < 128) {
        mb = g_blockmax[t * DOUT + c];
        mred[t] = mb;
    }
    __syncthreads();
    for (int s = 64; s > 0; s >>= 1) {
        if (t < s) mred[t] = fmaxf(mred[t], mred[t + s]);
        __syncthreads();
    }
    const float M = mred[0];

    // scales + scaled denominator
    if (t < 128) {
        float sc = __expf(mb - M);
        sscale[t] = sc;
        dred[t] = sc * g_sumpart[t * DOUT + c];
    }
    __syncthreads();
    for (int s = 64; s > 0; s >>= 1) {
        if (t < s) dred[t] += dred[t + s];
        __syncthreads();
    }
    const float inv = 1.0f / dred[0];

    // scaled numerator: 8 sub-sums of 16 partials (fixed sets, fixed order)
    const int sub = t >> 5, j = t & 31;
    float s = 0.0f;
    const float* base = g_part + (size_t)c * DIN + d0 + j;
#pragma unroll 8
    for (int i = 0; i < 16; i++) {
        int b = sub + 8 * i;
        s += sscale[b] * base[(size_t)b * (DOUT * DIN)];
    }
    red2[sub * 32 + j] = s;
    __syncthreads();
    if (t < 32) {
        float r = 0.0f;
#pragma unroll
        for (int q = 0; q < 8; q++) r += red2[q * 32 + t];
        out[c * DIN + d0 + t] = r * inv;
    }
}

extern "C" void kernel_launch(void* const* d_in, const int* in_sizes, int n_in,
                              void* d_out, int out_size)
{
    const float* X = (const float*)d_in[0];
    const float* A = (const float*)d_in[1];
    const float* W = (const float*)d_in[2];
    // d_in[3] = b: per-column constant -> softmax(axis 0) invariant -> dropped
    float* out = (float*)d_out;

    cudaFuncSetAttribute(gemm1_kernel,
                         cudaFuncAttributeMaxDynamicSharedMemorySize, GEMM1_SMEM);
    cudaFuncSetAttribute(gemm2_kernel,
                         cudaFuncAttributeMaxDynamicSharedMemorySize, GEMM2_SMEM);

    gemm1_kernel<<<NN / 64, 256, GEMM1_SMEM>>>(X, W);
    gemm2_kernel<<<NN / 64, 256, GEMM2_SMEM>>>(A, X);
    reduce_out_kernel<<<DOUT * 8, 256>>>(out);
}